// round 1
// baseline (speedup 1.0000x reference)
#include <cuda_runtime.h>

// TokenEmbedding segment-sum:
//   out[b, t, :] = sum over w with wordpiece_to_token[b, w] == t of x[b, w, :]
// wordpiece_to_token is sorted (non-decreasing) per batch row, so each token's
// wordpieces form a contiguous range found by binary search. One CTA per
// (b, t): search [lo, hi), sum rows with float4 loads, write exactly once
// (writing zeros for empty ranges -> no separate zero-init pass, no atomics).

#define B_DIM 8
#define L_DIM 4096
#define H_DIM 1024
#define H4 (H_DIM / 4)   // 256 float4 per row == blockDim.x

__device__ __forceinline__ int lower_bound_i32(const int* __restrict__ a, int n, int key) {
    int lo = 0, hi = n;
    while (lo < hi) {
        int mid = (lo + hi) >> 1;
        if (__ldg(a + mid) < key) lo = mid + 1;
        else                      hi = mid;
    }
    return lo;
}

__global__ __launch_bounds__(H4) void token_segsum_kernel(
    const float* __restrict__ x,      // [B, L, H]
    const int*   __restrict__ w2t,    // [B, L] sorted per row
    float*       __restrict__ out)    // [B, L, H]
{
    const int t = blockIdx.x;   // token id within row
    const int b = blockIdx.y;   // batch

    const int* idx = w2t + (size_t)b * L_DIM;

    __shared__ int s_lo, s_hi;
    // two independent searches on two different warps (overlap their latency)
    if (threadIdx.x == 0)  s_lo = lower_bound_i32(idx, L_DIM, t);
    if (threadIdx.x == 32) s_hi = lower_bound_i32(idx, L_DIM, t + 1);
    __syncthreads();

    const int lo = s_lo;
    const int hi = s_hi;

    const int c = threadIdx.x;  // float4 column 0..255
    const float4* __restrict__ rows =
        reinterpret_cast<const float4*>(x + (size_t)b * L_DIM * H_DIM);

    float4 acc = make_float4(0.f, 0.f, 0.f, 0.f);
    for (int w = lo; w < hi; ++w) {
        float4 v = __ldg(&rows[(size_t)w * H4 + c]);
        acc.x += v.x; acc.y += v.y; acc.z += v.z; acc.w += v.w;
    }

    float4* __restrict__ orow =
        reinterpret_cast<float4*>(out + ((size_t)b * L_DIM + t) * H_DIM);
    orow[c] = acc;
}

extern "C" void kernel_launch(void* const* d_in, const int* in_sizes, int n_in,
                              void* d_out, int out_size)
{
    const float* x   = (const float*)d_in[0];   // sequence_output [B,L,H] fp32
    const int*   w2t = (const int*)  d_in[1];   // wordpiece_to_token [B,L] int32
    float*       out = (float*)d_out;           // [B,L,H] fp32

    dim3 grid(L_DIM, B_DIM);
    token_segsum_kernel<<<grid, H4>>>(x, w2t, out);
}

// round 2
// speedup vs baseline: 1.8263x; 1.8263x over previous
#include <cuda_runtime.h>

// TokenEmbedding segment-sum, two-phase:
//   Phase A: scatter segment boundaries  start[b][t] = lower_bound(w2t[b], t)
//            (w2t sorted per batch; thread per wordpiece fills the jump range)
//   Phase B: one CTA per (b, t): rows [lo, hi) summed with float4 loads,
//            output written exactly once (zeros for empty tokens).
// No atomics, no binary search in the hot kernel, minimal DRAM traffic
// (read 128MB + write 128MB + ~KBs of index metadata).

#define B_DIM 8
#define L_DIM 4096
#define H_DIM 1024
#define H4 (H_DIM / 4)   // 256 float4 per row == blockDim.x of phase B

// scratch: segment start offsets, one extra slot per batch for the end sentinel
__device__ int g_seg_start[B_DIM][L_DIM + 1];

__global__ __launch_bounds__(256) void seg_bounds_kernel(
    const int* __restrict__ w2t)      // [B, L] sorted per row
{
    const int b = blockIdx.y;
    const int w = blockIdx.x * blockDim.x + threadIdx.x;
    if (w >= L_DIM) return;

    const int* idx = w2t + (size_t)b * L_DIM;
    const int cur  = __ldg(idx + w);
    const int prev = (w > 0) ? __ldg(idx + w - 1) : -1;

    // start[t] = w for every token t in (prev, cur]
    for (int t = prev + 1; t <= cur; ++t)
        g_seg_start[b][t] = w;

    // tail: tokens beyond the last wordpiece's token map to empty [L, L)
    if (w == L_DIM - 1) {
        for (int t = cur + 1; t <= L_DIM; ++t)
            g_seg_start[b][t] = L_DIM;
    }
}

__global__ __launch_bounds__(H4) void token_segsum_kernel(
    const float* __restrict__ x,      // [B, L, H]
    float*       __restrict__ out)    // [B, L, H]
{
    const int t = blockIdx.x;   // token id within row
    const int b = blockIdx.y;   // batch

    // broadcast loads (L1/L2 hit, same address across warp -> no conflict)
    const int lo = __ldg(&g_seg_start[b][t]);
    const int hi = __ldg(&g_seg_start[b][t + 1]);

    const int c = threadIdx.x;  // float4 column 0..255
    const float4* __restrict__ rows =
        reinterpret_cast<const float4*>(x + (size_t)b * L_DIM * H_DIM);

    float4 acc = make_float4(0.f, 0.f, 0.f, 0.f);
    for (int w = lo; w < hi; ++w) {
        float4 v = __ldg(&rows[(size_t)w * H4 + c]);
        acc.x += v.x; acc.y += v.y; acc.z += v.z; acc.w += v.w;
    }

    float4* __restrict__ orow =
        reinterpret_cast<float4*>(out + ((size_t)b * L_DIM + t) * H_DIM);
    orow[c] = acc;
}

extern "C" void kernel_launch(void* const* d_in, const int* in_sizes, int n_in,
                              void* d_out, int out_size)
{
    const float* x   = (const float*)d_in[0];   // sequence_output [B,L,H] fp32
    const int*   w2t = (const int*)  d_in[1];   // wordpiece_to_token [B,L] int32
    float*       out = (float*)d_out;           // [B,L,H] fp32

    dim3 gridA(L_DIM / 256, B_DIM);
    seg_bounds_kernel<<<gridA, 256>>>(w2t);

    dim3 gridB(L_DIM, B_DIM);
    token_segsum_kernel<<<gridB, H4>>>(x, out);
}